// round 1
// baseline (speedup 1.0000x reference)
#include <cuda_runtime.h>
#include <math.h>

#define HIDDEN 128
#define MAX_ING 20000
#define MAX_CMP 10000

// Scratch: precomputed per-node projections (fits L2: 10MB + 5MB)
__device__ float g_P_ing[MAX_ING * HIDDEN];
__device__ float g_P_cmp[MAX_CMP * HIDDEN];

__device__ __forceinline__ void fma4(float4& a, float xs, const float4 w) {
    a.x = fmaf(xs, w.x, a.x);
    a.y = fmaf(xs, w.y, a.y);
    a.z = fmaf(xs, w.z, a.z);
    a.w = fmaf(xs, w.w, a.w);
}

// P[row][j] = sum_k X[row][k] * W[k*128 + j]  (+ bias[j] if add_bias)
// Each warp computes 4 rows x 128 cols; lane owns 4 columns (float4).
// grid.x = ceil(nrows/32), block = 256 (8 warps)
__global__ void proj_kernel(const float* __restrict__ X,
                            const float* __restrict__ W,
                            const float* __restrict__ bias,
                            int nrows, int which, int add_bias)
{
    float* P = which ? g_P_cmp : g_P_ing;
    const int warp = threadIdx.x >> 5;
    const int lane = threadIdx.x & 31;
    const int row0 = blockIdx.x * 32 + warp * 4;
    if (row0 >= nrows) return;

    // clamp for tail (stores are guarded)
    const int r0 = row0;
    const int r1 = min(row0 + 1, nrows - 1);
    const int r2 = min(row0 + 2, nrows - 1);
    const int r3 = min(row0 + 3, nrows - 1);

    const float4* __restrict__ W4 = reinterpret_cast<const float4*>(W);  // [128][32]
    const float4* __restrict__ X4 = reinterpret_cast<const float4*>(X);  // [nrows][32]

    float4 acc0 = make_float4(0.f, 0.f, 0.f, 0.f);
    float4 acc1 = acc0, acc2 = acc0, acc3 = acc0;

    #pragma unroll 4
    for (int k4 = 0; k4 < 32; k4++) {
        // 4 consecutive k rows of W, this lane's 4 columns
        const float4 w0 = W4[(k4 * 4 + 0) * 32 + lane];
        const float4 w1 = W4[(k4 * 4 + 1) * 32 + lane];
        const float4 w2 = W4[(k4 * 4 + 2) * 32 + lane];
        const float4 w3 = W4[(k4 * 4 + 3) * 32 + lane];
        // x values for 4 rows (broadcast loads within warp)
        const float4 x0 = X4[r0 * 32 + k4];
        const float4 x1 = X4[r1 * 32 + k4];
        const float4 x2 = X4[r2 * 32 + k4];
        const float4 x3 = X4[r3 * 32 + k4];

        fma4(acc0, x0.x, w0); fma4(acc0, x0.y, w1); fma4(acc0, x0.z, w2); fma4(acc0, x0.w, w3);
        fma4(acc1, x1.x, w0); fma4(acc1, x1.y, w1); fma4(acc1, x1.z, w2); fma4(acc1, x1.w, w3);
        fma4(acc2, x2.x, w0); fma4(acc2, x2.y, w1); fma4(acc2, x2.z, w2); fma4(acc2, x2.w, w3);
        fma4(acc3, x3.x, w0); fma4(acc3, x3.y, w1); fma4(acc3, x3.z, w2); fma4(acc3, x3.w, w3);
    }

    if (add_bias) {
        const float4 bv = reinterpret_cast<const float4*>(bias)[lane];
        acc0.x += bv.x; acc0.y += bv.y; acc0.z += bv.z; acc0.w += bv.w;
        acc1.x += bv.x; acc1.y += bv.y; acc1.z += bv.z; acc1.w += bv.w;
        acc2.x += bv.x; acc2.y += bv.y; acc2.z += bv.z; acc2.w += bv.w;
        acc3.x += bv.x; acc3.y += bv.y; acc3.z += bv.z; acc3.w += bv.w;
    }

    float4* P4 = reinterpret_cast<float4*>(P);
    if (row0 + 0 < nrows) P4[(row0 + 0) * 32 + lane] = acc0;
    if (row0 + 1 < nrows) P4[(row0 + 1) * 32 + lane] = acc1;
    if (row0 + 2 < nrows) P4[(row0 + 2) * 32 + lane] = acc2;
    if (row0 + 3 < nrows) P4[(row0 + 3) * 32 + lane] = acc3;
}

// One warp per edge: gather 2x 512B vectors (L2-resident), relu(add), dot W2,
// warp reduce, sigmoid.
// grid.x = ceil(E/8), block = 256 (8 warps)
__global__ void edge_kernel(const int* __restrict__ ei,
                            const float* __restrict__ W2,
                            const float* __restrict__ b2,
                            float* __restrict__ out,
                            int E)
{
    const int e = blockIdx.x * 8 + (threadIdx.x >> 5);
    if (e >= E) return;
    const int lane = threadIdx.x & 31;

    const int s = __ldg(&ei[e]);
    const int d = __ldg(&ei[E + e]);

    const float4 a = reinterpret_cast<const float4*>(g_P_ing)[s * 32 + lane];
    const float4 b = reinterpret_cast<const float4*>(g_P_cmp)[d * 32 + lane];
    const float4 w = __ldg(reinterpret_cast<const float4*>(W2) + lane);

    const float hx = fmaxf(a.x + b.x, 0.f);
    const float hy = fmaxf(a.y + b.y, 0.f);
    const float hz = fmaxf(a.z + b.z, 0.f);
    const float hw = fmaxf(a.w + b.w, 0.f);

    float dot = hx * w.x + hy * w.y + hz * w.z + hw * w.w;
    #pragma unroll
    for (int o = 16; o > 0; o >>= 1)
        dot += __shfl_xor_sync(0xFFFFFFFFu, dot, o);

    if (lane == 0) {
        const float z = dot + __ldg(b2);
        out[e] = 1.f / (1.f + expf(-z));
    }
}

extern "C" void kernel_launch(void* const* d_in, const int* in_sizes, int n_in,
                              void* d_out, int out_size)
{
    const float* x_ing = (const float*)d_in[0];
    const float* x_cmp = (const float*)d_in[1];
    const int*   ei    = (const int*)d_in[2];
    const float* W1    = (const float*)d_in[3];
    const float* b1    = (const float*)d_in[4];
    const float* W2    = (const float*)d_in[5];
    const float* b2    = (const float*)d_in[6];
    float* out = (float*)d_out;

    const int n_ing = in_sizes[0] / HIDDEN;
    const int n_cmp = in_sizes[1] / HIDDEN;
    const int E     = in_sizes[2] / 2;

    // P_ing = x_ing @ W1[:128]          (no bias)
    proj_kernel<<<(n_ing + 31) / 32, 256>>>(x_ing, W1, b1, n_ing, 0, 0);
    // P_cmp = x_cmp @ W1[128:] + b1     (bias folded here)
    proj_kernel<<<(n_cmp + 31) / 32, 256>>>(x_cmp, W1 + HIDDEN * HIDDEN, b1, n_cmp, 1, 1);
    // out = sigmoid(relu(P_ing[s] + P_cmp[d]) . W2 + b2)
    edge_kernel<<<(E + 7) / 8, 256>>>(ei, W2, b2, out, E);
}

// round 2
// speedup vs baseline: 1.0117x; 1.0117x over previous
#include <cuda_runtime.h>
#include <cuda_bf16.h>
#include <math.h>

#define HIDDEN 128
#define MAX_ING 20000
#define MAX_CMP 10000

// Precomputed per-node projections in bf16 (L2-resident: 5MB + 2.5MB)
__device__ __nv_bfloat16 g_P_ing[MAX_ING * HIDDEN];
__device__ __nv_bfloat16 g_P_cmp[MAX_CMP * HIDDEN];

__device__ __forceinline__ void fma4(float4& a, float xs, const float4 w) {
    a.x = fmaf(xs, w.x, a.x);
    a.y = fmaf(xs, w.y, a.y);
    a.z = fmaf(xs, w.z, a.z);
    a.w = fmaf(xs, w.w, a.w);
}

// Fused projection of both node tables.
// Blocks [0, blocks_ing): P_ing = x_ing @ W1[:128]        (no bias)
// Blocks [blocks_ing, ..): P_cmp = x_cmp @ W1[128:] + b1  (bias folded)
// Each warp computes 8 rows x 128 cols; lane owns 4 columns (float4).
// block = 256 (8 warps) -> 64 rows per block.
__global__ void __launch_bounds__(256) proj_kernel(
    const float* __restrict__ x_ing,
    const float* __restrict__ x_cmp,
    const float* __restrict__ W1,
    const float* __restrict__ b1,
    int n_ing, int n_cmp, int blocks_ing)
{
    const bool is_cmp = (blockIdx.x >= blocks_ing);
    const float* __restrict__ X = is_cmp ? x_cmp : x_ing;
    const float* __restrict__ W = is_cmp ? (W1 + HIDDEN * HIDDEN) : W1;
    __nv_bfloat16* __restrict__ P = is_cmp ? g_P_cmp : g_P_ing;
    const int nrows = is_cmp ? n_cmp : n_ing;
    const int bid = is_cmp ? (blockIdx.x - blocks_ing) : blockIdx.x;

    const int warp = threadIdx.x >> 5;
    const int lane = threadIdx.x & 31;
    const int row0 = bid * 64 + warp * 8;
    if (row0 >= nrows) return;

    // clamped row indices for the tail (stores guarded)
    int r[8];
    #pragma unroll
    for (int i = 0; i < 8; i++) r[i] = min(row0 + i, nrows - 1);

    const float4* __restrict__ W4 = reinterpret_cast<const float4*>(W);  // [128][32]
    const float4* __restrict__ X4 = reinterpret_cast<const float4*>(X);  // [nrows][32]

    float4 acc[8];
    #pragma unroll
    for (int i = 0; i < 8; i++) acc[i] = make_float4(0.f, 0.f, 0.f, 0.f);

    #pragma unroll 2
    for (int k4 = 0; k4 < 32; k4++) {
        const float4 w0 = W4[(k4 * 4 + 0) * 32 + lane];
        const float4 w1 = W4[(k4 * 4 + 1) * 32 + lane];
        const float4 w2 = W4[(k4 * 4 + 2) * 32 + lane];
        const float4 w3 = W4[(k4 * 4 + 3) * 32 + lane];
        #pragma unroll
        for (int i = 0; i < 8; i++) {
            const float4 x = X4[r[i] * 32 + k4];  // warp-broadcast load
            fma4(acc[i], x.x, w0);
            fma4(acc[i], x.y, w1);
            fma4(acc[i], x.z, w2);
            fma4(acc[i], x.w, w3);
        }
    }

    if (is_cmp) {
        const float4 bv = reinterpret_cast<const float4*>(b1)[lane];
        #pragma unroll
        for (int i = 0; i < 8; i++) {
            acc[i].x += bv.x; acc[i].y += bv.y;
            acc[i].z += bv.z; acc[i].w += bv.w;
        }
    }

    // store as bf16: 4 values per lane = 8 bytes (uint2)
    uint2* P2 = reinterpret_cast<uint2*>(P);
    #pragma unroll
    for (int i = 0; i < 8; i++) {
        if (row0 + i < nrows) {
            __nv_bfloat162 lo = __float22bfloat162_rn(make_float2(acc[i].x, acc[i].y));
            __nv_bfloat162 hi = __float22bfloat162_rn(make_float2(acc[i].z, acc[i].w));
            uint2 v;
            v.x = *reinterpret_cast<unsigned int*>(&lo);
            v.y = *reinterpret_cast<unsigned int*>(&hi);
            P2[r[i] * 32 + lane] = v;
        }
    }
}

// One warp per edge: gather 2x 256B bf16 vectors (L2-resident), relu(add),
// dot with W2, warp reduce, sigmoid.
// grid.x = ceil(E/8), block = 256 (8 warps)
__global__ void __launch_bounds__(256) edge_kernel(
    const int* __restrict__ ei,
    const float* __restrict__ W2,
    const float* __restrict__ b2,
    float* __restrict__ out,
    int E)
{
    const int e = blockIdx.x * 8 + (threadIdx.x >> 5);
    if (e >= E) return;
    const int lane = threadIdx.x & 31;

    const int s = __ldg(&ei[e]);
    const int d = __ldg(&ei[E + e]);

    const uint2 pa = reinterpret_cast<const uint2*>(g_P_ing)[s * 32 + lane];
    const uint2 pb = reinterpret_cast<const uint2*>(g_P_cmp)[d * 32 + lane];
    const float4 w = __ldg(reinterpret_cast<const float4*>(W2) + lane);

    const float2 a01 = __bfloat1622float2(*reinterpret_cast<const __nv_bfloat162*>(&pa.x));
    const float2 a23 = __bfloat1622float2(*reinterpret_cast<const __nv_bfloat162*>(&pa.y));
    const float2 b01 = __bfloat1622float2(*reinterpret_cast<const __nv_bfloat162*>(&pb.x));
    const float2 b23 = __bfloat1622float2(*reinterpret_cast<const __nv_bfloat162*>(&pb.y));

    const float h0 = fmaxf(a01.x + b01.x, 0.f);
    const float h1 = fmaxf(a01.y + b01.y, 0.f);
    const float h2 = fmaxf(a23.x + b23.x, 0.f);
    const float h3 = fmaxf(a23.y + b23.y, 0.f);

    float dot = h0 * w.x + h1 * w.y + h2 * w.z + h3 * w.w;
    #pragma unroll
    for (int o = 16; o > 0; o >>= 1)
        dot += __shfl_xor_sync(0xFFFFFFFFu, dot, o);

    if (lane == 0) {
        const float z = dot + __ldg(b2);
        out[e] = 1.f / (1.f + expf(-z));
    }
}

extern "C" void kernel_launch(void* const* d_in, const int* in_sizes, int n_in,
                              void* d_out, int out_size)
{
    const float* x_ing = (const float*)d_in[0];
    const float* x_cmp = (const float*)d_in[1];
    const int*   ei    = (const int*)d_in[2];
    const float* W1    = (const float*)d_in[3];
    const float* b1    = (const float*)d_in[4];
    const float* W2    = (const float*)d_in[5];
    const float* b2    = (const float*)d_in[6];
    float* out = (float*)d_out;

    const int n_ing = in_sizes[0] / HIDDEN;
    const int n_cmp = in_sizes[1] / HIDDEN;
    const int E     = in_sizes[2] / 2;

    const int blocks_ing = (n_ing + 63) / 64;
    const int blocks_cmp = (n_cmp + 63) / 64;

    proj_kernel<<<blocks_ing + blocks_cmp, 256>>>(x_ing, x_cmp, W1, b1,
                                                  n_ing, n_cmp, blocks_ing);
    edge_kernel<<<(E + 7) / 8, 256>>>(ei, W2, b2, out, E);
}

// round 3
// speedup vs baseline: 1.4308x; 1.4143x over previous
#include <cuda_runtime.h>
#include <cuda_bf16.h>
#include <math.h>

#define HIDDEN 128
#define MAX_ING 20000
#define MAX_CMP 10000

// Precomputed per-node projections in bf16 (L2-resident: 5MB + 2.5MB)
__device__ __nv_bfloat16 g_P_ing[MAX_ING * HIDDEN];
__device__ __nv_bfloat16 g_P_cmp[MAX_CMP * HIDDEN];

__device__ __forceinline__ void fma4(float4& a, float xs, const float4 w) {
    a.x = fmaf(xs, w.x, a.x);
    a.y = fmaf(xs, w.y, a.y);
    a.z = fmaf(xs, w.z, a.z);
    a.w = fmaf(xs, w.w, a.w);
}

// Fused projection of both node tables (unchanged from R2; ~17us, not the wall).
__global__ void __launch_bounds__(256) proj_kernel(
    const float* __restrict__ x_ing,
    const float* __restrict__ x_cmp,
    const float* __restrict__ W1,
    const float* __restrict__ b1,
    int n_ing, int n_cmp, int blocks_ing)
{
    const bool is_cmp = (blockIdx.x >= blocks_ing);
    const float* __restrict__ X = is_cmp ? x_cmp : x_ing;
    const float* __restrict__ W = is_cmp ? (W1 + HIDDEN * HIDDEN) : W1;
    __nv_bfloat16* __restrict__ P = is_cmp ? g_P_cmp : g_P_ing;
    const int nrows = is_cmp ? n_cmp : n_ing;
    const int bid = is_cmp ? (blockIdx.x - blocks_ing) : blockIdx.x;

    const int warp = threadIdx.x >> 5;
    const int lane = threadIdx.x & 31;
    const int row0 = bid * 64 + warp * 8;
    if (row0 >= nrows) return;

    int r[8];
    #pragma unroll
    for (int i = 0; i < 8; i++) r[i] = min(row0 + i, nrows - 1);

    const float4* __restrict__ W4 = reinterpret_cast<const float4*>(W);  // [128][32]
    const float4* __restrict__ X4 = reinterpret_cast<const float4*>(X);  // [nrows][32]

    float4 acc[8];
    #pragma unroll
    for (int i = 0; i < 8; i++) acc[i] = make_float4(0.f, 0.f, 0.f, 0.f);

    #pragma unroll 2
    for (int k4 = 0; k4 < 32; k4++) {
        const float4 w0 = W4[(k4 * 4 + 0) * 32 + lane];
        const float4 w1 = W4[(k4 * 4 + 1) * 32 + lane];
        const float4 w2 = W4[(k4 * 4 + 2) * 32 + lane];
        const float4 w3 = W4[(k4 * 4 + 3) * 32 + lane];
        #pragma unroll
        for (int i = 0; i < 8; i++) {
            const float4 x = X4[r[i] * 32 + k4];
            fma4(acc[i], x.x, w0);
            fma4(acc[i], x.y, w1);
            fma4(acc[i], x.z, w2);
            fma4(acc[i], x.w, w3);
        }
    }

    if (is_cmp) {
        const float4 bv = reinterpret_cast<const float4*>(b1)[lane];
        #pragma unroll
        for (int i = 0; i < 8; i++) {
            acc[i].x += bv.x; acc[i].y += bv.y;
            acc[i].z += bv.z; acc[i].w += bv.w;
        }
    }

    uint2* P2 = reinterpret_cast<uint2*>(P);
    #pragma unroll
    for (int i = 0; i < 8; i++) {
        if (row0 + i < nrows) {
            __nv_bfloat162 lo = __float22bfloat162_rn(make_float2(acc[i].x, acc[i].y));
            __nv_bfloat162 hi = __float22bfloat162_rn(make_float2(acc[i].z, acc[i].w));
            uint2 v;
            v.x = *reinterpret_cast<unsigned int*>(&lo);
            v.y = *reinterpret_cast<unsigned int*>(&hi);
            P2[r[i] * 32 + lane] = v;
        }
    }
}

// ---------------------------------------------------------------------------
// Edge kernel v3: 8 lanes per edge, 4 edges per 8-lane group.
// Each lane owns 16 columns (32B = 2x uint4 per table). add+relu in packed
// bf16 (HADD2/HMAX2), unpack, fp32 FFMA dot, 3-shuffle reduce within group.
// block = 256 -> 32 groups -> 128 edges per block.
// ---------------------------------------------------------------------------

// dot of lane's 16-column slice for one edge
__device__ __forceinline__ float edge_slice_dot(
    int s, int d, int t,
    const float4 w0, const float4 w1, const float4 w2, const float4 w3)
{
    const char* pa = (const char*)g_P_ing + (size_t)s * 256 + t * 32;
    const char* pb = (const char*)g_P_cmp + (size_t)d * 256 + t * 32;
    const uint4 a0 = *reinterpret_cast<const uint4*>(pa);
    const uint4 a1 = *reinterpret_cast<const uint4*>(pa + 16);
    const uint4 b0 = *reinterpret_cast<const uint4*>(pb);
    const uint4 b1 = *reinterpret_cast<const uint4*>(pb + 16);

    const __nv_bfloat162 z2 = __float2bfloat162_rn(0.f);
    float acc = 0.f;

    const unsigned* au = &a0.x;  // a0/a1 contiguous? not guaranteed; handle explicitly
    const unsigned av[8] = {a0.x, a0.y, a0.z, a0.w, a1.x, a1.y, a1.z, a1.w};
    const unsigned bv[8] = {b0.x, b0.y, b0.z, b0.w, b1.x, b1.y, b1.z, b1.w};
    const float wv[16] = {w0.x, w0.y, w0.z, w0.w,
                          w1.x, w1.y, w1.z, w1.w,
                          w2.x, w2.y, w2.z, w2.w,
                          w3.x, w3.y, w3.z, w3.w};
    (void)au;

    #pragma unroll
    for (int j = 0; j < 8; j++) {
        __nv_bfloat162 ha = *reinterpret_cast<const __nv_bfloat162*>(&av[j]);
        __nv_bfloat162 hb = *reinterpret_cast<const __nv_bfloat162*>(&bv[j]);
        __nv_bfloat162 h = __hmax2(__hadd2(ha, hb), z2);      // add + relu in bf16
        float2 f = __bfloat1622float2(h);
        acc = fmaf(f.x, wv[2 * j], acc);
        acc = fmaf(f.y, wv[2 * j + 1], acc);
    }
    return acc;
}

__global__ void __launch_bounds__(256) edge_kernel(
    const int* __restrict__ ei,
    const float* __restrict__ W2,
    const float* __restrict__ b2,
    float* __restrict__ out,
    int E)
{
    const int gid = (blockIdx.x * 256 + threadIdx.x) >> 3;  // global group id
    const int t = threadIdx.x & 7;                           // sublane in group
    const int e0 = gid * 4;
    if (e0 >= E) return;

    // this lane's 16 W2 coefficients (columns 16t .. 16t+15)
    const float4* W24 = reinterpret_cast<const float4*>(W2);
    const float4 w0 = __ldg(W24 + t * 4 + 0);
    const float4 w1 = __ldg(W24 + t * 4 + 1);
    const float4 w2 = __ldg(W24 + t * 4 + 2);
    const float4 w3 = __ldg(W24 + t * 4 + 3);
    const float b2v = __ldg(b2);

    int sv[4], dv[4];
    int ne;  // edges handled by this group
    if (e0 + 4 <= E) {
        ne = 4;
        const int4 s4 = __ldg(reinterpret_cast<const int4*>(ei + e0));
        const int4 d4 = __ldg(reinterpret_cast<const int4*>(ei + E + e0));
        sv[0] = s4.x; sv[1] = s4.y; sv[2] = s4.z; sv[3] = s4.w;
        dv[0] = d4.x; dv[1] = d4.y; dv[2] = d4.z; dv[3] = d4.w;
    } else {
        ne = E - e0;
        for (int i = 0; i < ne; i++) {
            sv[i] = __ldg(ei + e0 + i);
            dv[i] = __ldg(ei + E + e0 + i);
        }
        for (int i = ne; i < 4; i++) { sv[i] = 0; dv[i] = 0; }
    }

    float acc[4];
    #pragma unroll
    for (int i = 0; i < 4; i++)
        acc[i] = edge_slice_dot(sv[i], dv[i], t, w0, w1, w2, w3);

    // reduce each edge's partial over the 8-lane group (xor 1,2,4 stays in group)
    #pragma unroll
    for (int i = 0; i < 4; i++) {
        acc[i] += __shfl_xor_sync(0xFFFFFFFFu, acc[i], 1);
        acc[i] += __shfl_xor_sync(0xFFFFFFFFu, acc[i], 2);
        acc[i] += __shfl_xor_sync(0xFFFFFFFFu, acc[i], 4);
    }

    if (t == 0) {
        #pragma unroll
        for (int i = 0; i < 4; i++) {
            if (i < ne) {
                const float z = acc[i] + b2v;
                out[e0 + i] = 1.f / (1.f + __expf(-z));
            }
        }
    }
}

extern "C" void kernel_launch(void* const* d_in, const int* in_sizes, int n_in,
                              void* d_out, int out_size)
{
    const float* x_ing = (const float*)d_in[0];
    const float* x_cmp = (const float*)d_in[1];
    const int*   ei    = (const int*)d_in[2];
    const float* W1    = (const float*)d_in[3];
    const float* b1    = (const float*)d_in[4];
    const float* W2    = (const float*)d_in[5];
    const float* b2    = (const float*)d_in[6];
    float* out = (float*)d_out;

    const int n_ing = in_sizes[0] / HIDDEN;
    const int n_cmp = in_sizes[1] / HIDDEN;
    const int E     = in_sizes[2] / 2;

    const int blocks_ing = (n_ing + 63) / 64;
    const int blocks_cmp = (n_cmp + 63) / 64;
    proj_kernel<<<blocks_ing + blocks_cmp, 256>>>(x_ing, x_cmp, W1, b1,
                                                  n_ing, n_cmp, blocks_ing);

    // 128 edges per block of 256 threads
    const int blocks = (E + 127) / 128;
    edge_kernel<<<blocks, 256>>>(ei, W2, b2, out, E);
}

// round 4
// speedup vs baseline: 1.6697x; 1.1670x over previous
#include <cuda_runtime.h>
#include <cuda_bf16.h>
#include <math.h>

#define HIDDEN 128
#define MAX_ING 20000
#define MAX_CMP 10000

// Precomputed per-node projections in bf16 (L2-resident: 5MB + 2.5MB)
__device__ __nv_bfloat16 g_P_ing[MAX_ING * HIDDEN];
__device__ __nv_bfloat16 g_P_cmp[MAX_CMP * HIDDEN];

__device__ __forceinline__ void fma4(float4& a, float xs, const float4 w) {
    a.x = fmaf(xs, w.x, a.x);
    a.y = fmaf(xs, w.y, a.y);
    a.z = fmaf(xs, w.z, a.z);
    a.w = fmaf(xs, w.w, a.w);
}

// Fused projection of both node tables (8 rows/warp register blocking).
__global__ void __launch_bounds__(256) proj_kernel(
    const float* __restrict__ x_ing,
    const float* __restrict__ x_cmp,
    const float* __restrict__ W1,
    const float* __restrict__ b1,
    int n_ing, int n_cmp, int blocks_ing)
{
    const bool is_cmp = (blockIdx.x >= blocks_ing);
    const float* __restrict__ X = is_cmp ? x_cmp : x_ing;
    const float* __restrict__ W = is_cmp ? (W1 + HIDDEN * HIDDEN) : W1;
    __nv_bfloat16* __restrict__ P = is_cmp ? g_P_cmp : g_P_ing;
    const int nrows = is_cmp ? n_cmp : n_ing;
    const int bid = is_cmp ? (blockIdx.x - blocks_ing) : blockIdx.x;

    const int warp = threadIdx.x >> 5;
    const int lane = threadIdx.x & 31;
    const int row0 = bid * 64 + warp * 8;
    if (row0 >= nrows) return;

    int r[8];
    #pragma unroll
    for (int i = 0; i < 8; i++) r[i] = min(row0 + i, nrows - 1);

    const float4* __restrict__ W4 = reinterpret_cast<const float4*>(W);  // [128][32]
    const float4* __restrict__ X4 = reinterpret_cast<const float4*>(X);  // [nrows][32]

    float4 acc[8];
    #pragma unroll
    for (int i = 0; i < 8; i++) acc[i] = make_float4(0.f, 0.f, 0.f, 0.f);

    #pragma unroll 2
    for (int k4 = 0; k4 < 32; k4++) {
        const float4 w0 = W4[(k4 * 4 + 0) * 32 + lane];
        const float4 w1 = W4[(k4 * 4 + 1) * 32 + lane];
        const float4 w2 = W4[(k4 * 4 + 2) * 32 + lane];
        const float4 w3 = W4[(k4 * 4 + 3) * 32 + lane];
        #pragma unroll
        for (int i = 0; i < 8; i++) {
            const float4 x = X4[r[i] * 32 + k4];
            fma4(acc[i], x.x, w0);
            fma4(acc[i], x.y, w1);
            fma4(acc[i], x.z, w2);
            fma4(acc[i], x.w, w3);
        }
    }

    if (is_cmp) {
        const float4 bv = reinterpret_cast<const float4*>(b1)[lane];
        #pragma unroll
        for (int i = 0; i < 8; i++) {
            acc[i].x += bv.x; acc[i].y += bv.y;
            acc[i].z += bv.z; acc[i].w += bv.w;
        }
    }

    uint2* P2 = reinterpret_cast<uint2*>(P);
    #pragma unroll
    for (int i = 0; i < 8; i++) {
        if (row0 + i < nrows) {
            __nv_bfloat162 lo = __float22bfloat162_rn(make_float2(acc[i].x, acc[i].y));
            __nv_bfloat162 hi = __float22bfloat162_rn(make_float2(acc[i].z, acc[i].w));
            uint2 v;
            v.x = *reinterpret_cast<unsigned int*>(&lo);
            v.y = *reinterpret_cast<unsigned int*>(&hi);
            P2[r[i] * 32 + lane] = v;
        }
    }
}

// ---------------------------------------------------------------------------
// Edge kernel v4: 8 lanes per edge, 4 edges per 8-lane group.
// CONTIGUOUS group loads: lane t reads bytes [16t,16t+16) of the row (low half,
// cols 8t..8t+8) and [128+16t, ...) (high half, cols 64+8t..64+8t+8).
// -> every 8-lane load = exactly one 128B line = 1 L1 wavefront, full sectors.
// ---------------------------------------------------------------------------

// dot of lane's 16 columns (8 low-half + 8 high-half) for one edge
__device__ __forceinline__ float edge_slice_dot(
    int s, int d, int t,
    const float4 wl0, const float4 wl1,   // W2 cols [8t, 8t+8)
    const float4 wh0, const float4 wh1)   // W2 cols [64+8t, 64+8t+8)
{
    const char* pa = (const char*)g_P_ing + (size_t)s * 256 + t * 16;
    const char* pb = (const char*)g_P_cmp + (size_t)d * 256 + t * 16;
    const uint4 al = *reinterpret_cast<const uint4*>(pa);         // line 0
    const uint4 ah = *reinterpret_cast<const uint4*>(pa + 128);   // line 1
    const uint4 bl = *reinterpret_cast<const uint4*>(pb);
    const uint4 bh = *reinterpret_cast<const uint4*>(pb + 128);

    const __nv_bfloat162 z2 = __float2bfloat162_rn(0.f);

    const unsigned av[8] = {al.x, al.y, al.z, al.w, ah.x, ah.y, ah.z, ah.w};
    const unsigned bv[8] = {bl.x, bl.y, bl.z, bl.w, bh.x, bh.y, bh.z, bh.w};
    const float wv[16] = {wl0.x, wl0.y, wl0.z, wl0.w,
                          wl1.x, wl1.y, wl1.z, wl1.w,
                          wh0.x, wh0.y, wh0.z, wh0.w,
                          wh1.x, wh1.y, wh1.z, wh1.w};

    float acc = 0.f;
    #pragma unroll
    for (int j = 0; j < 8; j++) {
        __nv_bfloat162 ha = *reinterpret_cast<const __nv_bfloat162*>(&av[j]);
        __nv_bfloat162 hb = *reinterpret_cast<const __nv_bfloat162*>(&bv[j]);
        __nv_bfloat162 h = __hmax2(__hadd2(ha, hb), z2);   // add + relu in bf16
        float2 f = __bfloat1622float2(h);
        acc = fmaf(f.x, wv[2 * j], acc);
        acc = fmaf(f.y, wv[2 * j + 1], acc);
    }
    return acc;
}

__global__ void __launch_bounds__(256) edge_kernel(
    const int* __restrict__ ei,
    const float* __restrict__ W2,
    const float* __restrict__ b2,
    float* __restrict__ out,
    int E)
{
    const int gid = (blockIdx.x * 256 + threadIdx.x) >> 3;  // global group id
    const int t = threadIdx.x & 7;                           // sublane in group
    const int e0 = gid * 4;
    if (e0 >= E) return;

    // lane's W2 coefficients: cols [8t,8t+8) and [64+8t,64+8t+8)
    const float4* W24 = reinterpret_cast<const float4*>(W2);
    const float4 wl0 = __ldg(W24 + 2 * t + 0);
    const float4 wl1 = __ldg(W24 + 2 * t + 1);
    const float4 wh0 = __ldg(W24 + 16 + 2 * t + 0);
    const float4 wh1 = __ldg(W24 + 16 + 2 * t + 1);
    const float b2v = __ldg(b2);

    int sv[4], dv[4];
    int ne;
    if (e0 + 4 <= E) {
        ne = 4;
        const int4 s4 = __ldg(reinterpret_cast<const int4*>(ei + e0));
        const int4 d4 = __ldg(reinterpret_cast<const int4*>(ei + E + e0));
        sv[0] = s4.x; sv[1] = s4.y; sv[2] = s4.z; sv[3] = s4.w;
        dv[0] = d4.x; dv[1] = d4.y; dv[2] = d4.z; dv[3] = d4.w;
    } else {
        ne = E - e0;
        for (int i = 0; i < ne; i++) {
            sv[i] = __ldg(ei + e0 + i);
            dv[i] = __ldg(ei + E + e0 + i);
        }
        for (int i = ne; i < 4; i++) { sv[i] = 0; dv[i] = 0; }
    }

    float acc[4];
    #pragma unroll
    for (int i = 0; i < 4; i++)
        acc[i] = edge_slice_dot(sv[i], dv[i], t, wl0, wl1, wh0, wh1);

    #pragma unroll
    for (int i = 0; i < 4; i++) {
        acc[i] += __shfl_xor_sync(0xFFFFFFFFu, acc[i], 1);
        acc[i] += __shfl_xor_sync(0xFFFFFFFFu, acc[i], 2);
        acc[i] += __shfl_xor_sync(0xFFFFFFFFu, acc[i], 4);
    }

    if (t == 0) {
        #pragma unroll
        for (int i = 0; i < 4; i++) {
            if (i < ne) {
                const float z = acc[i] + b2v;
                out[e0 + i] = 1.f / (1.f + __expf(-z));
            }
        }
    }
}

extern "C" void kernel_launch(void* const* d_in, const int* in_sizes, int n_in,
                              void* d_out, int out_size)
{
    const float* x_ing = (const float*)d_in[0];
    const float* x_cmp = (const float*)d_in[1];
    const int*   ei    = (const int*)d_in[2];
    const float* W1    = (const float*)d_in[3];
    const float* b1    = (const float*)d_in[4];
    const float* W2    = (const float*)d_in[5];
    const float* b2    = (const float*)d_in[6];
    float* out = (float*)d_out;

    const int n_ing = in_sizes[0] / HIDDEN;
    const int n_cmp = in_sizes[1] / HIDDEN;
    const int E     = in_sizes[2] / 2;

    const int blocks_ing = (n_ing + 63) / 64;
    const int blocks_cmp = (n_cmp + 63) / 64;
    proj_kernel<<<blocks_ing + blocks_cmp, 256>>>(x_ing, x_cmp, W1, b1,
                                                  n_ing, n_cmp, blocks_ing);

    const int blocks = (E + 127) / 128;  // 128 edges per 256-thread block
    edge_kernel<<<blocks, 256>>>(ei, W2, b2, out, E);
}